// round 1
// baseline (speedup 1.0000x reference)
#include <cuda_runtime.h>

#define NUM_CLASSES 1000
#define FEAT_DIM 512
#define BATCH 65536

// Scratch accumulators (no cudaMalloc allowed).
__device__ float g_sums[NUM_CLASSES];
__device__ unsigned int g_counts[NUM_CLASSES];

__global__ void cl_zero_kernel() {
    int i = blockIdx.x * blockDim.x + threadIdx.x;
    if (i < NUM_CLASSES) {
        g_sums[i] = 0.0f;
        g_counts[i] = 0u;
    }
}

// One warp per sample row. 256 threads = 8 rows per block.
__global__ void __launch_bounds__(256) cl_accum_kernel(
    const float* __restrict__ features,
    const float* __restrict__ centers,
    const long long* __restrict__ labels)
{
    int warp = threadIdx.x >> 5;
    int lane = threadIdx.x & 31;
    int row = blockIdx.x * 8 + warp;
    if (row >= BATCH) return;

    int lab = (int)labels[row];

    const float4* frow = reinterpret_cast<const float4*>(features + (size_t)row * FEAT_DIM);
    const float4* crow = reinterpret_cast<const float4*>(centers + (size_t)lab * FEAT_DIM);

    float acc = 0.0f;
#pragma unroll
    for (int i = 0; i < 4; i++) {
        float4 a = frow[lane + i * 32];
        float4 b = crow[lane + i * 32];
        float dx = a.x - b.x;
        float dy = a.y - b.y;
        float dz = a.z - b.z;
        float dw = a.w - b.w;
        acc += dx * dx + dy * dy + dz * dz + dw * dw;
    }

#pragma unroll
    for (int o = 16; o; o >>= 1)
        acc += __shfl_xor_sync(0xffffffffu, acc, o);

    if (lane == 0) {
        atomicAdd(&g_sums[lab], acc);
        atomicAdd(&g_counts[lab], 1u);
    }
}

// Single block: per-class normalize + reduce to scalar.
__global__ void __launch_bounds__(1024) cl_finish_kernel(float* __restrict__ out) {
    __shared__ float red[32];
    int tid = threadIdx.x;

    float v = 0.0f;
    if (tid < NUM_CLASSES) {
        unsigned int cnt = g_counts[tid];
        if (cnt > 0u)
            v = g_sums[tid] / ((float)cnt * (float)FEAT_DIM);
    }

#pragma unroll
    for (int o = 16; o; o >>= 1)
        v += __shfl_xor_sync(0xffffffffu, v, o);
    if ((tid & 31) == 0) red[tid >> 5] = v;
    __syncthreads();

    if (tid < 32) {
        v = red[tid];
#pragma unroll
        for (int o = 16; o; o >>= 1)
            v += __shfl_xor_sync(0xffffffffu, v, o);
        if (tid == 0)
            out[0] = v / (float)BATCH;
    }
}

extern "C" void kernel_launch(void* const* d_in, const int* in_sizes, int n_in,
                              void* d_out, int out_size) {
    const float* features = (const float*)d_in[0];
    const float* centers = (const float*)d_in[1];
    const long long* labels = (const long long*)d_in[2];
    float* out = (float*)d_out;

    cl_zero_kernel<<<4, 256>>>();
    cl_accum_kernel<<<BATCH / 8, 256>>>(features, centers, labels);
    cl_finish_kernel<<<1, 1024>>>(out);
}

// round 2
// speedup vs baseline: 2.6133x; 2.6133x over previous
#include <cuda_runtime.h>

#define NUM_CLASSES 1000
#define FEAT_DIM 512
#define BATCH 65536
#define HIST_BLOCKS 64
#define HIST_THREADS 256
#define MAIN_THREADS 512           // 16 warps = 16 rows per block
#define MAIN_BLOCKS (BATCH / 16)   // 4096

__device__ int g_cnt[NUM_CLASSES];

// K0: zero class counts + the output scalar (d_out is poisoned each replay).
__global__ void cl_init_kernel(float* __restrict__ out) {
    int i = blockIdx.x * blockDim.x + threadIdx.x;
    if (i < NUM_CLASSES) g_cnt[i] = 0;
    if (i == 0) out[0] = 0.0f;
}

// K1: label histogram. 64 blocks, privatized smem hist, one global REDG pass.
__global__ void __launch_bounds__(HIST_THREADS) cl_hist_kernel(
    const long long* __restrict__ labels)
{
    __shared__ int h[NUM_CLASSES];
    for (int c = threadIdx.x; c < NUM_CLASSES; c += HIST_THREADS) h[c] = 0;
    __syncthreads();

    // Each block handles BATCH/HIST_BLOCKS = 1024 labels; 4 per thread via longlong2.
    const longlong2* lab2 =
        reinterpret_cast<const longlong2*>(labels + (size_t)blockIdx.x * (BATCH / HIST_BLOCKS));
#pragma unroll
    for (int i = 0; i < 2; i++) {
        longlong2 v = lab2[threadIdx.x * 2 + i];
        atomicAdd(&h[(int)v.x], 1);
        atomicAdd(&h[(int)v.y], 1);
    }
    __syncthreads();

    for (int c = threadIdx.x; c < NUM_CLASSES; c += HIST_THREADS) {
        int n = h[c];
        if (n) atomicAdd(&g_cnt[c], n);
    }
}

// K2: one warp per row. Streaming (evict-first) feature loads, cached center
// loads, per-row weight 1/(cnt*512*65536), block-reduce, one atomic per block.
__global__ void __launch_bounds__(MAIN_THREADS) cl_main_kernel(
    const float* __restrict__ features,
    const float* __restrict__ centers,
    const long long* __restrict__ labels,
    float* __restrict__ out)
{
    __shared__ float red[MAIN_THREADS / 32];
    int warp = threadIdx.x >> 5;
    int lane = threadIdx.x & 31;
    int row = blockIdx.x * (MAIN_THREADS / 32) + warp;

    int lab = (int)labels[row];  // warp-uniform broadcast load

    const float4* frow = reinterpret_cast<const float4*>(features + (size_t)row * FEAT_DIM);
    const float4* crow = reinterpret_cast<const float4*>(centers + (size_t)lab * FEAT_DIM);

    float acc = 0.0f;
#pragma unroll
    for (int i = 0; i < 4; i++) {
        float4 a = __ldcs(frow + lane + i * 32);  // evict-first: don't thrash L2
        float4 b = __ldg(crow + lane + i * 32);   // keep centers L2/L1 resident
        float dx = a.x - b.x;
        float dy = a.y - b.y;
        float dz = a.z - b.z;
        float dw = a.w - b.w;
        acc += dx * dx + dy * dy + dz * dz + dw * dw;
    }

#pragma unroll
    for (int o = 16; o; o >>= 1)
        acc += __shfl_xor_sync(0xffffffffu, acc, o);

    if (lane == 0) {
        int cnt = g_cnt[lab];  // cnt >= 1 (this row is counted)
        float w = __fdividef(1.0f, (float)cnt * (float)FEAT_DIM) * (1.0f / (float)BATCH);
        red[warp] = acc * w;
    }
    __syncthreads();

    if (warp == 0) {
        float v = (lane < MAIN_THREADS / 32) ? red[lane] : 0.0f;
#pragma unroll
        for (int o = 8; o; o >>= 1)
            v += __shfl_xor_sync(0xffffffffu, v, o);
        if (lane == 0)
            atomicAdd(out, v);
    }
}

extern "C" void kernel_launch(void* const* d_in, const int* in_sizes, int n_in,
                              void* d_out, int out_size) {
    const float* features = (const float*)d_in[0];
    const float* centers = (const float*)d_in[1];
    const long long* labels = (const long long*)d_in[2];
    float* out = (float*)d_out;

    cl_init_kernel<<<1, 1024>>>(out);
    cl_hist_kernel<<<HIST_BLOCKS, HIST_THREADS>>>(labels);
    cl_main_kernel<<<MAIN_BLOCKS, MAIN_THREADS>>>(features, centers, labels, out);
}